// round 17
// baseline (speedup 1.0000x reference)
#include <cuda_runtime.h>
#include <cuda_bf16.h>
#include <cuda_fp16.h>
#include <math.h>
#include <cstdint>

// Problem dims
#define LL 512
#define BB 64
#define II 256
#define HH 512
#define G4 2048   // 4*H

// ---------------- scratch (static device globals; no allocation) ----------------
__device__ float g_gates_f[(size_t)LL * BB * G4];     // [t][b][4H]
__device__ float g_gates_r[(size_t)LL * BB * G4];     // [t][b][4H]
__device__ unsigned g_bar4[4 * 32];                   // 4 group barriers, 128B apart

// h state as SINGLE fp16: [dir][parity][b][u]
__device__ __align__(16) __half g_sh16[2 * 2 * BB * HH];

// fp16 GEMM operands
__device__ __align__(16) __half g_Af16[(size_t)LL * BB * 2 * HH];
__device__ __align__(16) __half g_Wf16f[(size_t)G4 * 2 * HH];
__device__ __align__(16) __half g_Wf16r[(size_t)G4 * 2 * HH];
__device__ __align__(16) __half g_Whf16f[(size_t)G4 * HH];
__device__ __align__(16) __half g_Whf16r[(size_t)G4 * HH];

__device__ __forceinline__ uint32_t smem_u32(const void* p) {
    uint32_t a;
    asm("{ .reg .u64 t; cvta.to.shared.u64 t, %1; cvt.u32.u64 %0, t; }" : "=r"(a) : "l"(p));
    return a;
}

__device__ __forceinline__ float fsig(float x) {
    return 1.0f / (1.0f + __expf(-x));
}
__device__ __forceinline__ float ftanh(float x) {
    return fmaf(2.0f, fsig(2.0f * x), -1.0f);
}

// ---------------- transpose + convert: x[b][l][i] fp32 -> Af16[l*BB+b][i] fp16 ----------------
__global__ void transpose_cvt_x(const float4* __restrict__ x, __half2* __restrict__ xT) {
    int idx = blockIdx.x * blockDim.x + threadIdx.x;
    int i4 = idx & 63;
    int m  = idx >> 6;
    int t  = m >> 6;
    int b  = m & 63;
    float4 v = x[((size_t)(b * LL + t)) * 64 + i4];
    xT[idx * 2 + 0] = __floats2half2_rn(v.x, v.y);
    xT[idx * 2 + 1] = __floats2half2_rn(v.z, v.w);
}

// ---------------- fp32 -> fp16 convert ----------------
__global__ void cvt_f16(const float4* __restrict__ src, __half2* __restrict__ dst, int n4) {
    int i = blockIdx.x * blockDim.x + threadIdx.x;
    if (i >= n4) return;
    float4 v = src[i];
    dst[i * 2 + 0] = __floats2half2_rn(v.x, v.y);
    dst[i * 2 + 1] = __floats2half2_rn(v.z, v.w);
}

// ---------------- plain fp16 GEMM (unchanged, known-good) ----------------
#define GBK   32
#define GTILE 10240
#define GSTG  (2 * GTILE)
#define GB_SMEM (2 * GSTG + 512)

__global__ __launch_bounds__(256, 2) void gemm_f16(
    int M, int N, int K,
    const __half* __restrict__ A,
    const __half* __restrict__ B,
    const float* __restrict__ bias1, const float* __restrict__ bias2,
    float* __restrict__ C)
{
    extern __shared__ char sm[];
    uint32_t sb = smem_u32(sm);
    int tid  = threadIdx.x;
    int lane = tid & 31;
    int warp = tid >> 5;
    int gid  = lane >> 2;
    int tg   = lane & 3;
    int wm   = warp >> 2;
    int wn   = warp & 3;
    int n0   = blockIdx.x * 128;
    int m0   = blockIdx.y * 128;

    float* shb = (float*)(sm + 2 * GSTG);
    if (tid < 128) shb[tid] = bias1[n0 + tid] + bias2[n0 + tid];

    const char* srcs[2];
    srcs[0] = (const char*)(A + (size_t)m0 * K);
    srcs[1] = (const char*)(B + (size_t)n0 * K);

#define LOAD_STAGE(kc, bufsel)                                                      \
    {                                                                               \
        _Pragma("unroll")                                                           \
        for (int j = 0; j < 4; j++) {                                               \
            int c    = tid + j * 256;                                               \
            int tile = c >> 9;                                                      \
            int cc   = c & 511;                                                     \
            int row  = cc >> 2, g = cc & 3;                                         \
            uint32_t d = sb + (bufsel) * GSTG + tile * GTILE + row * 80 + g * 16;   \
            const char* s = srcs[tile] + ((size_t)row * K + (kc) * GBK) * 2 + g * 16; \
            asm volatile("cp.async.ca.shared.global [%0], [%1], 16;" :: "r"(d), "l"(s)); \
        }                                                                           \
        asm volatile("cp.async.commit_group;" ::: "memory");                        \
    }

    float acc[4][4][4];
#pragma unroll
    for (int i = 0; i < 4; i++)
#pragma unroll
        for (int j = 0; j < 4; j++)
#pragma unroll
            for (int r = 0; r < 4; r++) acc[i][j][r] = 0.0f;

    int nk = K / GBK;
    LOAD_STAGE(0, 0);
    LOAD_STAGE(1, 1);

    for (int kc = 0; kc < nk; kc++) {
        if (kc + 1 < nk)
            asm volatile("cp.async.wait_group 1;" ::: "memory");
        else
            asm volatile("cp.async.wait_group 0;" ::: "memory");
        __syncthreads();

        int buf = kc & 1;
        uint32_t bA = sb + buf * GSTG;
        uint32_t bB = bA + GTILE;

        uint32_t aoff = (uint32_t)(wm * 64 + (lane & 15)) * 80 + (lane >> 4) * 16;
        uint32_t boff = (uint32_t)(wn * 32 + (lane & 7)) * 80 + ((lane >> 3) & 1) * 16;

#pragma unroll
        for (int ks = 0; ks < 2; ks++) {
            uint32_t ko = ks * 32;
            uint32_t af[4][4];
#pragma unroll
            for (int mt = 0; mt < 4; mt++) {
                asm volatile("ldmatrix.sync.aligned.m8n8.x4.shared.b16 {%0,%1,%2,%3}, [%4];"
                    : "=r"(af[mt][0]), "=r"(af[mt][1]), "=r"(af[mt][2]), "=r"(af[mt][3])
                    : "r"(bA + aoff + ko + mt * (16 * 80)));
            }
            uint32_t bfr[4][2];
#pragma unroll
            for (int nt = 0; nt < 4; nt++) {
                asm volatile("ldmatrix.sync.aligned.m8n8.x2.shared.b16 {%0,%1}, [%2];"
                    : "=r"(bfr[nt][0]), "=r"(bfr[nt][1]) : "r"(bB + boff + ko + nt * (8 * 80)));
            }
#pragma unroll
            for (int mt = 0; mt < 4; mt++)
#pragma unroll
                for (int nt = 0; nt < 4; nt++) {
                    asm volatile(
                        "mma.sync.aligned.m16n8k16.row.col.f32.f16.f16.f32 "
                        "{%0,%1,%2,%3}, {%4,%5,%6,%7}, {%8,%9}, {%0,%1,%2,%3};"
                        : "+f"(acc[mt][nt][0]), "+f"(acc[mt][nt][1]),
                          "+f"(acc[mt][nt][2]), "+f"(acc[mt][nt][3])
                        : "r"(af[mt][0]), "r"(af[mt][1]), "r"(af[mt][2]), "r"(af[mt][3]),
                          "r"(bfr[nt][0]), "r"(bfr[nt][1]));
                }
        }
        __syncthreads();
        if (kc + 2 < nk) LOAD_STAGE(kc + 2, buf);
    }

#pragma unroll
    for (int mt = 0; mt < 4; mt++) {
        int r0 = m0 + wm * 64 + mt * 16 + gid;
#pragma unroll
        for (int nt = 0; nt < 4; nt++) {
            int cl = wn * 32 + nt * 8 + 2 * tg;
            float b0 = shb[cl], b1 = shb[cl + 1];
            *(float2*)(C + (size_t)r0 * N + n0 + cl) =
                make_float2(acc[mt][nt][0] + b0, acc[mt][nt][1] + b1);
            *(float2*)(C + (size_t)(r0 + 8) * N + n0 + cl) =
                make_float2(acc[mt][nt][2] + b0, acc[mt][nt][3] + b1);
        }
    }
}

// ---------------- persistent LSTM layer: shuffle epilogue, 3 syncs/step ----------------
// Grid 128 = dir(2) x us(32: 16 units) x bs(2: 32 batches), 2 CTAs/SM.
// W rows permuted in smem so fragment row-pair (r, r+8) = two gates of the same
// unit: r -> g=(r&1)|((r>>3)<<1), ul=(r>>1)&3. One shfl.bfly(4) gives each thread
// all 4 gates of its (unit, 2 batches) -> no gate-partial smem buffer, one less sync.
#define RP     1040
#define OFF_A  0
#define OFF_B  (64 * RP)
#define RK_SMEM (64 * RP + 32 * RP)          // 99840; x2 CTAs = 199.7KB

__global__ __launch_bounds__(256, 2) void lstm_layer_tc(
    const float* __restrict__ gates_f,
    const float* __restrict__ gates_r,
    const __half* __restrict__ Whf16f, const __half* __restrict__ Whf16r,
    __half* __restrict__ sh16,
    void* __restrict__ outbuf,
    int out_mode)
{
    extern __shared__ char sm[];
    uint32_t sb = smem_u32(sm);
    int tid  = threadIdx.x;
    int lane = tid & 31;
    int warp = tid >> 5;
    int gid  = lane >> 2;
    int tg   = lane & 3;

    int bx  = blockIdx.x;
    int dir = bx >> 6;
    int us  = (bx >> 1) & 31;
    int bs  = bx & 1;
    int u0  = us * 16;
    int b0  = bs * 32;
    int grp = dir * 2 + bs;
    unsigned* gbar = (unsigned*)&g_bar4[grp * 32];

    const float* gates = dir ? gates_r : gates_f;
    const __half* wh = dir ? Whf16r : Whf16f;

    // ---- stage Whh slice once, rows PERMUTED: R=wm*16+r -> (g,ul) ----
#pragma unroll
    for (int j = 0; j < 16; j++) {
        int idx = tid + j * 256;
        int R   = idx >> 6;             // 0..63
        int ch  = idx & 63;
        int wmq = R >> 4;
        int r   = R & 15;
        int g   = (r & 1) | ((r >> 3) << 1);
        int ul  = wmq * 4 + ((r >> 1) & 3);
        size_t soff = (size_t)(g * HH + u0 + ul) * HH + ch * 8;
        *(uint4*)(sm + OFF_A + R * RP + ch * 16) = *(const uint4*)(wh + soff);
    }

    // 8 warps = 4m x 2n
    int wm = warp >> 1;
    int wn = warp & 1;
    uint32_t apat = (uint32_t)(lane & 15) * RP + (lane >> 4) * 16;
    uint32_t bpat = (uint32_t)((lane & 7) + ((lane >> 4) << 3)) * RP + ((lane >> 3) & 1) * 16;
    uint32_t aBase = sb + OFF_A + wm * 16 * RP + apat;
    uint32_t bBase = sb + OFF_B + wn * 16 * RP + bpat;

    // epilogue ownership (from fragment layout): unit + 2 batches per thread
    int g_lo   = gid & 1;                         // gates (g_lo, g_lo+2) held
    int ul     = (gid >> 1) & 3;
    int uown   = u0 + wm * 4 + ul;
    int nf_own = g_lo;                            // even: nf 0, odd: nf 1
    int bb0    = b0 + wn * 16 + nf_own * 8 + 2 * tg;
    float cst0 = 0.0f, cst1 = 0.0f;

    // gate prefetch for s = 0
    float pgA[4], pgB[4];
    {
        int t0i = dir ? (LL - 1) : 0;
        size_t base = ((size_t)t0i * BB + bb0) * G4 + uown;
#pragma unroll
        for (int g = 0; g < 4; g++) {
            pgA[g] = __ldcg(&gates[base + g * HH]);
            pgB[g] = __ldcg(&gates[base + G4 + g * HH]);
        }
    }

    for (int s = 0; s < LL; s++) {
        int t   = dir ? (LL - 1 - s) : s;
        int par = s & 1;
        const __half* hin  = sh16 + ((dir * 2 + par) * BB) * HH;
        __half*       hout = sh16 + ((dir * 2 + (par ^ 1)) * BB) * HH;

        // ---- wait for h(s) (arrivals of step s-1) ----
        if (tid == 0 && s > 0) {
            unsigned target = (unsigned)s * 32u;
            unsigned v;
            do {
                asm volatile("ld.acquire.gpu.global.u32 %0, [%1];"
                             : "=r"(v) : "l"(gbar) : "memory");
            } while (v < target);
        }
        __syncthreads();

        // ---- stage h tile (32 b x 512 fp16) ----
#pragma unroll
        for (int j = 0; j < 8; j++) {
            int idx = tid + j * 256;
            int row = idx >> 6;
            int ch  = idx & 63;
            uint4 v = __ldcg((const uint4*)(hin + (size_t)(b0 + row) * HH + ch * 8));
            *(uint4*)(sm + OFF_B + row * RP + ch * 16) = v;
        }
        __syncthreads();

        // ---- MMA: full K, dual accumulator chains ----
        float t0[2][4], t1[2][4];
#pragma unroll
        for (int j = 0; j < 2; j++)
#pragma unroll
            for (int r = 0; r < 4; r++) { t0[j][r] = 0.f; t1[j][r] = 0.f; }

#pragma unroll 8
        for (int kc = 0; kc < 32; kc += 2) {
            uint32_t kb0 = (uint32_t)kc * 32;
            uint32_t kb1 = kb0 + 32;
            uint32_t af0[4], af1[4], bf0[4], bf1[4];
            asm volatile("ldmatrix.sync.aligned.m8n8.x4.shared.b16 {%0,%1,%2,%3}, [%4];"
                : "=r"(af0[0]), "=r"(af0[1]), "=r"(af0[2]), "=r"(af0[3]) : "r"(aBase + kb0));
            asm volatile("ldmatrix.sync.aligned.m8n8.x4.shared.b16 {%0,%1,%2,%3}, [%4];"
                : "=r"(bf0[0]), "=r"(bf0[1]), "=r"(bf0[2]), "=r"(bf0[3]) : "r"(bBase + kb0));
            asm volatile("ldmatrix.sync.aligned.m8n8.x4.shared.b16 {%0,%1,%2,%3}, [%4];"
                : "=r"(af1[0]), "=r"(af1[1]), "=r"(af1[2]), "=r"(af1[3]) : "r"(aBase + kb1));
            asm volatile("ldmatrix.sync.aligned.m8n8.x4.shared.b16 {%0,%1,%2,%3}, [%4];"
                : "=r"(bf1[0]), "=r"(bf1[1]), "=r"(bf1[2]), "=r"(bf1[3]) : "r"(bBase + kb1));
#pragma unroll
            for (int nf = 0; nf < 2; nf++) {
                asm volatile(
                    "mma.sync.aligned.m16n8k16.row.col.f32.f16.f16.f32 "
                    "{%0,%1,%2,%3}, {%4,%5,%6,%7}, {%8,%9}, {%0,%1,%2,%3};"
                    : "+f"(t0[nf][0]), "+f"(t0[nf][1]), "+f"(t0[nf][2]), "+f"(t0[nf][3])
                    : "r"(af0[0]), "r"(af0[1]), "r"(af0[2]), "r"(af0[3]),
                      "r"(bf0[nf * 2]), "r"(bf0[nf * 2 + 1]));
                asm volatile(
                    "mma.sync.aligned.m16n8k16.row.col.f32.f16.f16.f32 "
                    "{%0,%1,%2,%3}, {%4,%5,%6,%7}, {%8,%9}, {%0,%1,%2,%3};"
                    : "+f"(t1[nf][0]), "+f"(t1[nf][1]), "+f"(t1[nf][2]), "+f"(t1[nf][3])
                    : "r"(af1[0]), "r"(af1[1]), "r"(af1[2]), "r"(af1[3]),
                      "r"(bf1[nf * 2]), "r"(bf1[nf * 2 + 1]));
            }
        }

        float own[4], oth[4];
        {
            int nf_o = nf_own ^ 1;
#pragma unroll
            for (int r = 0; r < 4; r++) {
                own[r] = t0[nf_own][r] + t1[nf_own][r];
                float send = t0[nf_o][r] + t1[nf_o][r];
                oth[r] = __shfl_xor_sync(0xFFFFFFFFu, send, 4);
            }
        }

        // ---- epilogue: all 4 gates in registers; 2 batches (bb0, bb0+1) ----
        {
            float gi0, gf0, gg0, go0, gi1, gf1, gg1, go1;
            if (g_lo == 0) {
                gi0 = own[0]; gg0 = own[2]; gf0 = oth[0]; go0 = oth[2];
                gi1 = own[1]; gg1 = own[3]; gf1 = oth[1]; go1 = oth[3];
            } else {
                gf0 = own[0]; go0 = own[2]; gi0 = oth[0]; gg0 = oth[2];
                gf1 = own[1]; go1 = own[3]; gi1 = oth[1]; gg1 = oth[3];
            }
            gi0 += pgA[0]; gf0 += pgA[1]; gg0 += pgA[2]; go0 += pgA[3];
            gi1 += pgB[0]; gf1 += pgB[1]; gg1 += pgB[2]; go1 += pgB[3];
            float si0 = fsig(gi0), si1 = fsig(gi1);
            float sf0 = fsig(gf0), sf1 = fsig(gf1);
            float so0 = fsig(go0), so1 = fsig(go1);
            cst0 = sf0 * cst0 + si0 * ftanh(gg0);
            cst1 = sf1 * cst1 + si1 * ftanh(gg1);
            float h20 = so0 * ftanh(cst0);
            float h21 = so1 * ftanh(cst1);
            __half hv0 = __float2half_rn(h20);
            __half hv1 = __float2half_rn(h21);
            __stcg(&hout[(size_t)bb0 * HH + uown], hv0);
            __stcg(&hout[(size_t)(bb0 + 1) * HH + uown], hv1);
            if (out_mode) {
                ((float*)outbuf)[((size_t)bb0 * LL + t) * (2 * HH) + dir * HH + uown] = h20;
                ((float*)outbuf)[((size_t)(bb0 + 1) * LL + t) * (2 * HH) + dir * HH + uown] = h21;
            } else {
                ((__half*)outbuf)[((size_t)t * BB + bb0) * (2 * HH) + dir * HH + uown] = hv0;
                ((__half*)outbuf)[((size_t)t * BB + bb0 + 1) * (2 * HH) + dir * HH + uown] = hv1;
            }
        }

        // ---- prefetch gates for s+1 (overlaps barrier) ----
        if (s + 1 < LL) {
            int tn = dir ? (LL - 2 - s) : (s + 1);
            size_t base = ((size_t)tn * BB + bb0) * G4 + uown;
#pragma unroll
            for (int g = 0; g < 4; g++) {
                pgA[g] = __ldcg(&gates[base + g * HH]);
                pgB[g] = __ldcg(&gates[base + G4 + g * HH]);
            }
        }

        // ---- arrive ----
        __syncthreads();
        if (tid == 0)
            asm volatile("red.release.gpu.global.add.u32 [%0], %1;"
                         :: "l"(gbar), "r"(1u) : "memory");
    }
}

// ---------------- host launcher ----------------
extern "C" void kernel_launch(void* const* d_in, const int* in_sizes, int n_in,
                              void* d_out, int out_size)
{
    const float* x       = (const float*)d_in[0];
    const float* Wih_f0  = (const float*)d_in[1];
    const float* Whh_f0  = (const float*)d_in[2];
    const float* bih_f0  = (const float*)d_in[3];
    const float* bhh_f0  = (const float*)d_in[4];
    const float* Wih_r0  = (const float*)d_in[5];
    const float* Whh_r0  = (const float*)d_in[6];
    const float* bih_r0  = (const float*)d_in[7];
    const float* bhh_r0  = (const float*)d_in[8];
    const float* Wih_f1  = (const float*)d_in[9];
    const float* Whh_f1  = (const float*)d_in[10];
    const float* bih_f1  = (const float*)d_in[11];
    const float* bhh_f1  = (const float*)d_in[12];
    const float* Wih_r1  = (const float*)d_in[13];
    const float* Whh_r1  = (const float*)d_in[14];
    const float* bih_r1  = (const float*)d_in[15];
    const float* bhh_r1  = (const float*)d_in[16];

    float *gf, *gr;
    unsigned* bar4;
    __half *Af16, *Wf16f, *Wf16r, *Whf16f, *Whf16r, *sh16;
    cudaGetSymbolAddress((void**)&gf,     g_gates_f);
    cudaGetSymbolAddress((void**)&gr,     g_gates_r);
    cudaGetSymbolAddress((void**)&bar4,   g_bar4);
    cudaGetSymbolAddress((void**)&Af16,   g_Af16);
    cudaGetSymbolAddress((void**)&Wf16f,  g_Wf16f);
    cudaGetSymbolAddress((void**)&Wf16r,  g_Wf16r);
    cudaGetSymbolAddress((void**)&Whf16f, g_Whf16f);
    cudaGetSymbolAddress((void**)&Whf16r, g_Whf16r);
    cudaGetSymbolAddress((void**)&sh16,   g_sh16);

    cudaFuncSetAttribute(gemm_f16,      cudaFuncAttributeMaxDynamicSharedMemorySize, GB_SMEM);
    cudaFuncSetAttribute(lstm_layer_tc, cudaFuncAttributeMaxDynamicSharedMemorySize, RK_SMEM);

    const int M = LL * BB;   // 32768
    const int whn4 = (G4 * HH) / 4;

    transpose_cvt_x<<<8192, 256>>>((const float4*)x, (__half2*)Af16);

    dim3 ggrid(G4 / 128, M / 128);   // (16, 256)

    // ---- layer 0 (K = 256) ----
    {
        int w4 = (G4 * II) / 4;
        cvt_f16<<<(w4 + 255) / 256, 256>>>((const float4*)Wih_f0, (__half2*)Wf16f, w4);
        cvt_f16<<<(w4 + 255) / 256, 256>>>((const float4*)Wih_r0, (__half2*)Wf16r, w4);
        gemm_f16<<<ggrid, 256, GB_SMEM>>>(M, G4, II, Af16, Wf16f, bih_f0, bhh_f0, gf);
        gemm_f16<<<ggrid, 256, GB_SMEM>>>(M, G4, II, Af16, Wf16r, bih_r0, bhh_r0, gr);
        cvt_f16<<<(whn4 + 255) / 256, 256>>>((const float4*)Whh_f0, (__half2*)Whf16f, whn4);
        cvt_f16<<<(whn4 + 255) / 256, 256>>>((const float4*)Whh_r0, (__half2*)Whf16r, whn4);
    }
    cudaMemsetAsync(sh16, 0, sizeof(__half) * 2 * 2 * BB * HH, 0);
    cudaMemsetAsync(bar4, 0, sizeof(unsigned) * 4 * 32, 0);
    lstm_layer_tc<<<128, 256, RK_SMEM>>>(gf, gr, Whf16f, Whf16r, sh16, Af16, 0);

    // ---- layer 1 (K = 1024) ----
    {
        int w4 = (G4 * 2 * HH) / 4;
        cvt_f16<<<(w4 + 255) / 256, 256>>>((const float4*)Wih_f1, (__half2*)Wf16f, w4);
        cvt_f16<<<(w4 + 255) / 256, 256>>>((const float4*)Wih_r1, (__half2*)Wf16r, w4);
        gemm_f16<<<ggrid, 256, GB_SMEM>>>(M, G4, 2 * HH, Af16, Wf16f, bih_f1, bhh_f1, gf);
        gemm_f16<<<ggrid, 256, GB_SMEM>>>(M, G4, 2 * HH, Af16, Wf16r, bih_r1, bhh_r1, gr);
        cvt_f16<<<(whn4 + 255) / 256, 256>>>((const float4*)Whh_f1, (__half2*)Whf16f, whn4);
        cvt_f16<<<(whn4 + 255) / 256, 256>>>((const float4*)Whh_r1, (__half2*)Whf16r, whn4);
    }
    cudaMemsetAsync(sh16, 0, sizeof(__half) * 2 * 2 * BB * HH, 0);
    cudaMemsetAsync(bar4, 0, sizeof(unsigned) * 4 * 32, 0);
    lstm_layer_tc<<<128, 256, RK_SMEM>>>(gf, gr, Whf16f, Whf16r, sh16, d_out, 1);
}